// round 2
// baseline (speedup 1.0000x reference)
#include <cuda_runtime.h>
#include <cstdint>

#define B_ 16
#define Q_ 2048
#define S_ 2048
#define D_ 128

#define NEG_INF __int_as_float(0xff800000)

// mask dtype mode: 0 = uint8/bool, 1 = int32, 2 = float32
__device__ int g_mask_mode;

// ---------------------------------------------------------------------------
// Probe: classify mask buffer dtype from its first 1024 32-bit words.
//  int32 0/1   -> every word in {0,1}
//  float32 0/1 -> every word in {0, 0x3F800000}
//  uint8 0/1   -> words are packed bytes (e.g. 0x00010001), neither set
// ---------------------------------------------------------------------------
__global__ void k_probe_mask(const unsigned int* __restrict__ m)
{
    bool is_i32 = true, is_f32 = true;
    for (int i = 0; i < 1024; i++) {
        unsigned int w = m[i];
        if (w > 1u) is_i32 = false;
        if (w != 0u && w != 0x3F800000u) is_f32 = false;
    }
    g_mask_mode = is_i32 ? 1 : (is_f32 ? 2 : 0);
}

// ---------------------------------------------------------------------------
// Kernel 1: scores = (Q K^T) * D^-0.5, masked -> -inf, written to attention buf
// Tile 128(q) x 128(s), 256 threads, 8x8 micro-tile, D chunked by 32.
// Smem layout: [d][tile] (k-major) with XOR swizzle on the float4 column group.
// ---------------------------------------------------------------------------
__global__ __launch_bounds__(256) void k_scores(
    const float* __restrict__ Qm, const float* __restrict__ Km,
    const void* __restrict__ mask, float* __restrict__ P)
{
    __shared__ float As[32 * 128];  // [d][q]
    __shared__ float Bs[32 * 128];  // [d][s]

    const int b  = blockIdx.z;
    const int q0 = blockIdx.y * 128;
    const int s0 = blockIdx.x * 128;
    const float* Qb = Qm + ((size_t)b * Q_ + q0) * D_;
    const float* Kb = Km + ((size_t)b * S_ + s0) * D_;

    const int tid = threadIdx.x;
    const int tx = tid & 15;       // s dimension
    const int ty = tid >> 4;       // q dimension

    float acc[8][8];
#pragma unroll
    for (int i = 0; i < 8; i++)
#pragma unroll
        for (int j = 0; j < 8; j++) acc[i][j] = 0.f;

    for (int dc = 0; dc < D_; dc += 32) {
#pragma unroll
        for (int i = 0; i < 4; i++) {
            int idx = tid + i * 256;      // 0..1023
            int r   = idx >> 3;           // tile row 0..127
            int c4  = idx & 7;            // float4 group along d (0..7)
            float4 v = *(const float4*)(Qb + (size_t)r * D_ + dc + c4 * 4);
            float4 w = *(const float4*)(Kb + (size_t)r * D_ + dc + c4 * 4);
#pragma unroll
            for (int u = 0; u < 4; u++) {
                int d  = c4 * 4 + u;
                int pg = (r >> 2) ^ ((d >> 2) & 7);         // swizzled group
                int pc = (pg << 2) | (r & 3);
                As[d * 128 + pc] = ((const float*)&v)[u];
                Bs[d * 128 + pc] = ((const float*)&w)[u];
            }
        }
        __syncthreads();

#pragma unroll
        for (int k = 0; k < 32; k++) {
            int sw = (k >> 2) & 7;
            float4 a0 = *(const float4*)&As[k * 128 + (((ty * 2 + 0) ^ sw) << 2)];
            float4 a1 = *(const float4*)&As[k * 128 + (((ty * 2 + 1) ^ sw) << 2)];
            float4 b0 = *(const float4*)&Bs[k * 128 + (((tx * 2 + 0) ^ sw) << 2)];
            float4 b1 = *(const float4*)&Bs[k * 128 + (((tx * 2 + 1) ^ sw) << 2)];
            float a[8]  = {a0.x, a0.y, a0.z, a0.w, a1.x, a1.y, a1.z, a1.w};
            float bb[8] = {b0.x, b0.y, b0.z, b0.w, b1.x, b1.y, b1.z, b1.w};
#pragma unroll
            for (int i = 0; i < 8; i++)
#pragma unroll
                for (int j = 0; j < 8; j++)
                    acc[i][j] = fmaf(a[i], bb[j], acc[i][j]);
        }
        __syncthreads();
    }

    const float scale = 0.08838834764831845f;  // 128^-0.5
    const int mm = g_mask_mode;
#pragma unroll
    for (int i = 0; i < 8; i++) {
        int qq = q0 + ty * 8 + i;
        size_t base = ((size_t)b * Q_ + qq) * (size_t)S_ + s0 + tx * 8;

        bool mv[8];
        if (mm == 1) {
            const int* mi = (const int*)mask;
            int4 w0 = *(const int4*)(mi + base);
            int4 w1 = *(const int4*)(mi + base + 4);
            mv[0] = w0.x != 0; mv[1] = w0.y != 0; mv[2] = w0.z != 0; mv[3] = w0.w != 0;
            mv[4] = w1.x != 0; mv[5] = w1.y != 0; mv[6] = w1.z != 0; mv[7] = w1.w != 0;
        } else if (mm == 2) {
            const float* mf = (const float*)mask;
            float4 w0 = *(const float4*)(mf + base);
            float4 w1 = *(const float4*)(mf + base + 4);
            mv[0] = w0.x != 0.f; mv[1] = w0.y != 0.f; mv[2] = w0.z != 0.f; mv[3] = w0.w != 0.f;
            mv[4] = w1.x != 0.f; mv[5] = w1.y != 0.f; mv[6] = w1.z != 0.f; mv[7] = w1.w != 0.f;
        } else {
            const unsigned char* mu = (const unsigned char*)mask;
            uchar4 m0 = *(const uchar4*)(mu + base);
            uchar4 m1 = *(const uchar4*)(mu + base + 4);
            mv[0] = m0.x; mv[1] = m0.y; mv[2] = m0.z; mv[3] = m0.w;
            mv[4] = m1.x; mv[5] = m1.y; mv[6] = m1.z; mv[7] = m1.w;
        }

        float4 o0, o1;
        o0.x = mv[0] ? NEG_INF : acc[i][0] * scale;
        o0.y = mv[1] ? NEG_INF : acc[i][1] * scale;
        o0.z = mv[2] ? NEG_INF : acc[i][2] * scale;
        o0.w = mv[3] ? NEG_INF : acc[i][3] * scale;
        o1.x = mv[4] ? NEG_INF : acc[i][4] * scale;
        o1.y = mv[5] ? NEG_INF : acc[i][5] * scale;
        o1.z = mv[6] ? NEG_INF : acc[i][6] * scale;
        o1.w = mv[7] ? NEG_INF : acc[i][7] * scale;
        *(float4*)(P + base)     = o0;
        *(float4*)(P + base + 4) = o1;
    }
}

// ---------------------------------------------------------------------------
// Kernel 2: in-place row softmax over S=2048. One block (256 thr) per row.
// ---------------------------------------------------------------------------
__global__ __launch_bounds__(256) void k_softmax(float* __restrict__ P)
{
    __shared__ float red[8];
    const size_t row = blockIdx.x;
    float* p = P + row * (size_t)S_;
    const int tid  = threadIdx.x;
    const int lane = tid & 31;
    const int wid  = tid >> 5;

    float4 v0 = ((const float4*)p)[tid];
    float4 v1 = ((const float4*)p)[tid + 256];

    float m = fmaxf(fmaxf(fmaxf(v0.x, v0.y), fmaxf(v0.z, v0.w)),
                    fmaxf(fmaxf(v1.x, v1.y), fmaxf(v1.z, v1.w)));
#pragma unroll
    for (int o = 16; o; o >>= 1) m = fmaxf(m, __shfl_xor_sync(0xffffffffu, m, o));
    if (lane == 0) red[wid] = m;
    __syncthreads();
    m = red[0];
#pragma unroll
    for (int w = 1; w < 8; w++) m = fmaxf(m, red[w]);
    __syncthreads();

    float e[8];
    e[0] = __expf(v0.x - m); e[1] = __expf(v0.y - m);
    e[2] = __expf(v0.z - m); e[3] = __expf(v0.w - m);
    e[4] = __expf(v1.x - m); e[5] = __expf(v1.y - m);
    e[6] = __expf(v1.z - m); e[7] = __expf(v1.w - m);
    float s = ((e[0] + e[1]) + (e[2] + e[3])) + ((e[4] + e[5]) + (e[6] + e[7]));
#pragma unroll
    for (int o = 16; o; o >>= 1) s += __shfl_xor_sync(0xffffffffu, s, o);
    if (lane == 0) red[wid] = s;
    __syncthreads();
    s = red[0];
#pragma unroll
    for (int w = 1; w < 8; w++) s += red[w];

    const float inv = 1.0f / s;
    v0.x = e[0] * inv; v0.y = e[1] * inv; v0.z = e[2] * inv; v0.w = e[3] * inv;
    v1.x = e[4] * inv; v1.y = e[5] * inv; v1.z = e[6] * inv; v1.w = e[7] * inv;
    ((float4*)p)[tid]       = v0;
    ((float4*)p)[tid + 256] = v1;
}

// ---------------------------------------------------------------------------
// Kernel 3: out = P @ V.  Tile 64(q) x 128(d), K-loop over S in chunks of 32.
// 256 threads, 4x8 micro-tile. Ps transposed k-major, Vs natural; both swizzled.
// ---------------------------------------------------------------------------
__global__ __launch_bounds__(256) void k_pv(
    const float* __restrict__ P, const float* __restrict__ V,
    float* __restrict__ O)
{
    __shared__ float Ps[32 * 64];    // [s_k][q]
    __shared__ float Vs[32 * 128];   // [s_k][d]

    const int b  = blockIdx.y;
    const int q0 = blockIdx.x * 64;
    const float* Pb = P + ((size_t)b * Q_ + q0) * (size_t)S_;
    const float* Vb = V + (size_t)b * S_ * D_;

    const int tid = threadIdx.x;
    const int tx = tid & 15;      // d dimension (8 cols each)
    const int ty = tid >> 4;      // q dimension (4 rows each)

    float acc[4][8];
#pragma unroll
    for (int i = 0; i < 4; i++)
#pragma unroll
        for (int j = 0; j < 8; j++) acc[i][j] = 0.f;

    for (int sc = 0; sc < S_; sc += 32) {
        // load P chunk: 64 q-rows x 32 s, transposed into Ps[s][q]
#pragma unroll
        for (int i = 0; i < 2; i++) {
            int idx = tid + i * 256;   // 0..511
            int r   = idx >> 3;        // q row 0..63
            int c4  = idx & 7;         // s float4 group
            float4 v = *(const float4*)(Pb + (size_t)r * S_ + sc + c4 * 4);
#pragma unroll
            for (int u = 0; u < 4; u++) {
                int k  = c4 * 4 + u;
                int pg = (r >> 2) ^ ((k >> 2) & 7);
                int pc = (pg << 2) | (r & 3);
                Ps[k * 64 + pc] = ((const float*)&v)[u];
            }
        }
        // load V chunk: 32 s-rows x 128 d, natural layout, swizzled groups
#pragma unroll
        for (int i = 0; i < 4; i++) {
            int idx = tid + i * 256;   // 0..1023
            int r   = idx >> 5;        // s row 0..31
            int c4  = idx & 31;        // d float4 group
            int pc4 = (c4 & ~7) | ((c4 ^ ((r >> 2) & 7)) & 7);
            *(float4*)&Vs[r * 128 + pc4 * 4] =
                *(const float4*)(Vb + (size_t)(sc + r) * D_ + c4 * 4);
        }
        __syncthreads();

#pragma unroll
        for (int k = 0; k < 32; k++) {
            int sw = (k >> 2) & 7;
            float4 a4 = *(const float4*)&Ps[k * 64 + ((ty ^ sw) << 2)];
            int g0 = tx * 2, g1 = tx * 2 + 1;
            int p0 = (g0 & ~7) | ((g0 ^ sw) & 7);
            int p1 = (g1 & ~7) | ((g1 ^ sw) & 7);
            float4 b0 = *(const float4*)&Vs[k * 128 + (p0 << 2)];
            float4 b1 = *(const float4*)&Vs[k * 128 + (p1 << 2)];
            float a[4]  = {a4.x, a4.y, a4.z, a4.w};
            float bb[8] = {b0.x, b0.y, b0.z, b0.w, b1.x, b1.y, b1.z, b1.w};
#pragma unroll
            for (int i = 0; i < 4; i++)
#pragma unroll
                for (int j = 0; j < 8; j++)
                    acc[i][j] = fmaf(a[i], bb[j], acc[i][j]);
        }
        __syncthreads();
    }

#pragma unroll
    for (int i = 0; i < 4; i++) {
        int qq = q0 + ty * 4 + i;
        float* orow = O + ((size_t)b * Q_ + qq) * D_ + tx * 8;
        float4 o0 = {acc[i][0], acc[i][1], acc[i][2], acc[i][3]};
        float4 o1 = {acc[i][4], acc[i][5], acc[i][6], acc[i][7]};
        *(float4*)orow       = o0;
        *(float4*)(orow + 4) = o1;
    }
}

// ---------------------------------------------------------------------------
extern "C" void kernel_launch(void* const* d_in, const int* in_sizes, int n_in,
                              void* d_out, int out_size)
{
    // Identify mask by its element count (B*Q*S); remaining three keep
    // dict order: value, key, query.
    const size_t MASK_N = (size_t)B_ * Q_ * S_;
    const void* mask = nullptr;
    const float* vkq[3] = {nullptr, nullptr, nullptr};
    int nv = 0;
    for (int i = 0; i < n_in; i++) {
        if ((size_t)in_sizes[i] == MASK_N && mask == nullptr) {
            mask = d_in[i];
        } else if (nv < 3) {
            vkq[nv++] = (const float*)d_in[i];
        }
    }
    const float* value = vkq[0];
    const float* key   = vkq[1];
    const float* query = vkq[2];

    float* out  = (float*)d_out;
    float* attn = out + (size_t)B_ * Q_ * D_;   // (out, attention) tuple layout

    k_probe_mask<<<1, 1>>>((const unsigned int*)mask);

    dim3 g1(S_ / 128, Q_ / 128, B_);
    k_scores<<<g1, 256>>>(query, key, mask, attn);

    k_softmax<<<B_ * Q_, 256>>>(attn);

    dim3 g3(Q_ / 64, B_);
    k_pv<<<g3, 256>>>(attn, value, out);
}

// round 3
// speedup vs baseline: 1.7815x; 1.7815x over previous
#include <cuda_runtime.h>
#include <cuda_bf16.h>
#include <cstdint>

#define B_ 16
#define Q_ 2048
#define S_ 2048
#define D_ 128
#define NEG_INF __int_as_float(0xff800000)
#define STW 21   // smem row stride in 32-bit words for one 32-bf16 row (odd => conflict-free STS)

__device__ int g_mask_mode;   // 0 = uint8, 1 = int32, 2 = float32

// ---------------------------------------------------------------------------
__global__ void k_probe_mask(const unsigned int* __restrict__ m)
{
    bool is_i32 = true, is_f32 = true;
    for (int i = 0; i < 1024; i++) {
        unsigned int w = m[i];
        if (w > 1u) is_i32 = false;
        if (w != 0u && w != 0x3F800000u) is_f32 = false;
    }
    g_mask_mode = is_i32 ? 1 : (is_f32 ? 2 : 0);
}

// ---------------------------------------------------------------------------
__device__ __forceinline__ void split_pack(float x, float y, uint32_t& hi, uint32_t& lo)
{
    __nv_bfloat16 hx = __float2bfloat16_rn(x);
    __nv_bfloat16 hy = __float2bfloat16_rn(y);
    __nv_bfloat16 lx = __float2bfloat16_rn(x - __bfloat162float(hx));
    __nv_bfloat16 ly = __float2bfloat16_rn(y - __bfloat162float(hy));
    hi = (uint32_t)__bfloat16_as_ushort(hx) | ((uint32_t)__bfloat16_as_ushort(hy) << 16);
    lo = (uint32_t)__bfloat16_as_ushort(lx) | ((uint32_t)__bfloat16_as_ushort(ly) << 16);
}

__device__ __forceinline__ void mma16816(float (&c)[4], const uint32_t (&a)[4], const uint32_t (&b)[2])
{
    asm volatile(
        "mma.sync.aligned.m16n8k16.row.col.f32.bf16.bf16.f32 "
        "{%0,%1,%2,%3}, {%4,%5,%6,%7}, {%8,%9}, {%0,%1,%2,%3};\n"
        : "+f"(c[0]), "+f"(c[1]), "+f"(c[2]), "+f"(c[3])
        : "r"(a[0]), "r"(a[1]), "r"(a[2]), "r"(a[3]), "r"(b[0]), "r"(b[1]));
}

// ---------------------------------------------------------------------------
// Kernel 1: scores = mask ? -inf : (Q K^T) * D^-0.5   (3xBF16 tensor-core GEMM)
// CTA: 128q x 128s, 512 threads (16 warps: 4m x 4n grid, warp tile 32x32).
// ---------------------------------------------------------------------------
__global__ __launch_bounds__(512, 1) void k_scores(
    const float* __restrict__ Qm, const float* __restrict__ Km,
    const void* __restrict__ mask, float* __restrict__ P)
{
    __shared__ uint32_t sQh[128 * STW], sQl[128 * STW];
    __shared__ uint32_t sKh[128 * STW], sKl[128 * STW];

    const int b  = blockIdx.z;
    const int q0 = blockIdx.y * 128;
    const int s0 = blockIdx.x * 128;
    const float* Qb = Qm + ((size_t)b * Q_ + q0) * D_;
    const float* Kb = Km + ((size_t)b * S_ + s0) * D_;

    const int tid  = threadIdx.x;
    const int lane = tid & 31;
    const int wid  = tid >> 5;
    const int g    = lane >> 2;
    const int tg   = lane & 3;
    const int mw   = wid >> 2;
    const int nw   = wid & 3;

    float acc[2][4][4];
#pragma unroll
    for (int i = 0; i < 2; i++)
#pragma unroll
        for (int j = 0; j < 4; j++)
#pragma unroll
            for (int k = 0; k < 4; k++) acc[i][j][k] = 0.f;

    const int r0 = tid >> 3;       // 0..63
    const int c0 = tid & 7;        // float4 group within 32-float chunk row
    float4 pq0, pq1, pk0, pk1;

    pq0 = *(const float4*)(Qb + (size_t)r0 * D_ + c0 * 4);
    pq1 = *(const float4*)(Qb + (size_t)(r0 + 64) * D_ + c0 * 4);
    pk0 = *(const float4*)(Kb + (size_t)r0 * D_ + c0 * 4);
    pk1 = *(const float4*)(Kb + (size_t)(r0 + 64) * D_ + c0 * 4);

    for (int dc = 0; dc < D_; dc += 32) {
        {
            const int wb0 = r0 * STW + c0 * 2;
            const int wb1 = (r0 + 64) * STW + c0 * 2;
            uint32_t h, l;
            split_pack(pq0.x, pq0.y, h, l); sQh[wb0]     = h; sQl[wb0]     = l;
            split_pack(pq0.z, pq0.w, h, l); sQh[wb0 + 1] = h; sQl[wb0 + 1] = l;
            split_pack(pq1.x, pq1.y, h, l); sQh[wb1]     = h; sQl[wb1]     = l;
            split_pack(pq1.z, pq1.w, h, l); sQh[wb1 + 1] = h; sQl[wb1 + 1] = l;
            split_pack(pk0.x, pk0.y, h, l); sKh[wb0]     = h; sKl[wb0]     = l;
            split_pack(pk0.z, pk0.w, h, l); sKh[wb0 + 1] = h; sKl[wb0 + 1] = l;
            split_pack(pk1.x, pk1.y, h, l); sKh[wb1]     = h; sKl[wb1]     = l;
            split_pack(pk1.z, pk1.w, h, l); sKh[wb1 + 1] = h; sKl[wb1 + 1] = l;
        }
        __syncthreads();

        if (dc + 32 < D_) {
            pq0 = *(const float4*)(Qb + (size_t)r0 * D_ + dc + 32 + c0 * 4);
            pq1 = *(const float4*)(Qb + (size_t)(r0 + 64) * D_ + dc + 32 + c0 * 4);
            pk0 = *(const float4*)(Kb + (size_t)r0 * D_ + dc + 32 + c0 * 4);
            pk1 = *(const float4*)(Kb + (size_t)(r0 + 64) * D_ + dc + 32 + c0 * 4);
        }

#pragma unroll
        for (int ks = 0; ks < 2; ks++) {
            uint32_t ah[2][4], al[2][4];
#pragma unroll
            for (int mi = 0; mi < 2; mi++) {
                const int base = (mw * 32 + mi * 16 + g) * STW + ks * 8 + tg;
                ah[mi][0] = sQh[base];               al[mi][0] = sQl[base];
                ah[mi][1] = sQh[base + 8 * STW];     al[mi][1] = sQl[base + 8 * STW];
                ah[mi][2] = sQh[base + 4];           al[mi][2] = sQl[base + 4];
                ah[mi][3] = sQh[base + 8 * STW + 4]; al[mi][3] = sQl[base + 8 * STW + 4];
            }
#pragma unroll
            for (int nj = 0; nj < 4; nj++) {
                const int base = (nw * 32 + nj * 8 + g) * STW + ks * 8 + tg;
                uint32_t bh[2] = { sKh[base], sKh[base + 4] };
                uint32_t bl[2] = { sKl[base], sKl[base + 4] };
#pragma unroll
                for (int mi = 0; mi < 2; mi++) {
                    mma16816(acc[mi][nj], ah[mi], bh);
                    mma16816(acc[mi][nj], ah[mi], bl);
                    mma16816(acc[mi][nj], al[mi], bh);
                }
            }
        }
        __syncthreads();
    }

    const float scale = 0.08838834764831845f;  // 128^-0.5
    const int mm = g_mask_mode;
#pragma unroll
    for (int mi = 0; mi < 2; mi++) {
#pragma unroll
        for (int hh = 0; hh < 2; hh++) {
            const int q = q0 + mw * 32 + mi * 16 + hh * 8 + g;
            const size_t rowoff = ((size_t)b * Q_ + q) * (size_t)S_;
#pragma unroll
            for (int nj = 0; nj < 4; nj++) {
                const int s = s0 + nw * 32 + nj * 8 + tg * 2;
                const size_t off = rowoff + s;
                const float v0 = acc[mi][nj][hh * 2 + 0] * scale;
                const float v1 = acc[mi][nj][hh * 2 + 1] * scale;
                bool m0, m1;
                if (mm == 1) {
                    int2 w = *(const int2*)((const int*)mask + off);
                    m0 = w.x != 0; m1 = w.y != 0;
                } else if (mm == 2) {
                    float2 w = *(const float2*)((const float*)mask + off);
                    m0 = w.x != 0.f; m1 = w.y != 0.f;
                } else {
                    const unsigned char* mu = (const unsigned char*)mask + off;
                    m0 = mu[0] != 0; m1 = mu[1] != 0;
                }
                float2 o;
                o.x = m0 ? NEG_INF : v0;
                o.y = m1 ? NEG_INF : v1;
                *(float2*)(P + off) = o;
            }
        }
    }
}

// ---------------------------------------------------------------------------
// Kernel 2: in-place row softmax over S=2048. One block (256 thr) per row.
// ---------------------------------------------------------------------------
__global__ __launch_bounds__(256) void k_softmax(float* __restrict__ P)
{
    __shared__ float red[8];
    const size_t row = blockIdx.x;
    float* p = P + row * (size_t)S_;
    const int tid  = threadIdx.x;
    const int lane = tid & 31;
    const int wid  = tid >> 5;

    float4 v0 = ((const float4*)p)[tid];
    float4 v1 = ((const float4*)p)[tid + 256];

    float m = fmaxf(fmaxf(fmaxf(v0.x, v0.y), fmaxf(v0.z, v0.w)),
                    fmaxf(fmaxf(v1.x, v1.y), fmaxf(v1.z, v1.w)));
#pragma unroll
    for (int o = 16; o; o >>= 1) m = fmaxf(m, __shfl_xor_sync(0xffffffffu, m, o));
    if (lane == 0) red[wid] = m;
    __syncthreads();
    m = red[0];
#pragma unroll
    for (int w = 1; w < 8; w++) m = fmaxf(m, red[w]);
    __syncthreads();

    float e[8];
    e[0] = __expf(v0.x - m); e[1] = __expf(v0.y - m);
    e[2] = __expf(v0.z - m); e[3] = __expf(v0.w - m);
    e[4] = __expf(v1.x - m); e[5] = __expf(v1.y - m);
    e[6] = __expf(v1.z - m); e[7] = __expf(v1.w - m);
    float s = ((e[0] + e[1]) + (e[2] + e[3])) + ((e[4] + e[5]) + (e[6] + e[7]));
#pragma unroll
    for (int o = 16; o; o >>= 1) s += __shfl_xor_sync(0xffffffffu, s, o);
    if (lane == 0) red[wid] = s;
    __syncthreads();
    s = red[0];
#pragma unroll
    for (int w = 1; w < 8; w++) s += red[w];

    const float inv = 1.0f / s;
    v0.x = e[0] * inv; v0.y = e[1] * inv; v0.z = e[2] * inv; v0.w = e[3] * inv;
    v1.x = e[4] * inv; v1.y = e[5] * inv; v1.z = e[6] * inv; v1.w = e[7] * inv;
    ((float4*)p)[tid]       = v0;
    ((float4*)p)[tid + 256] = v1;
}

// ---------------------------------------------------------------------------
// Kernel 3: out = P @ V (3xBF16 tensor-core GEMM).
// CTA: 64q x 128d, 512 threads (16 warps: 4m x 4n, warp tile 16x32), S-chunks 32.
// V stored transposed [d][s] in smem so B-frag k-pairs are contiguous.
// ---------------------------------------------------------------------------
__global__ __launch_bounds__(512, 1) void k_pv(
    const float* __restrict__ P, const float* __restrict__ V,
    float* __restrict__ O)
{
    __shared__ uint32_t sPh[64 * STW],  sPl[64 * STW];
    __shared__ uint32_t sVh[128 * STW], sVl[128 * STW];

    const int b  = blockIdx.y;
    const int q0 = blockIdx.x * 64;
    const float* Pb = P + ((size_t)b * Q_ + q0) * (size_t)S_;
    const float* Vb = V + (size_t)b * S_ * D_;

    const int tid  = threadIdx.x;
    const int lane = tid & 31;
    const int wid  = tid >> 5;
    const int g    = lane >> 2;
    const int tg   = lane & 3;
    const int mw   = wid >> 2;
    const int nw   = wid & 3;

    float acc[4][4];
#pragma unroll
    for (int j = 0; j < 4; j++)
#pragma unroll
        for (int k = 0; k < 4; k++) acc[j][k] = 0.f;

    // P tile: 64 rows x 32 floats = 512 float4, 1 per thread
    const int pr = tid >> 3;       // 0..63
    const int pc = tid & 7;
    // V tile: d-coalesced loads: thread handles d = tid&127, sgroups sg and sg+4
    const int vd  = tid & 127;
    const int sg0 = tid >> 7;      // 0..3
    float4 pp;
    float vv0[4], vv1[4];

    pp = *(const float4*)(Pb + (size_t)pr * S_ + pc * 4);
#pragma unroll
    for (int k = 0; k < 4; k++) {
        vv0[k] = Vb[(size_t)(sg0 * 4 + k) * D_ + vd];
        vv1[k] = Vb[(size_t)((sg0 + 4) * 4 + k) * D_ + vd];
    }

    for (int sc = 0; sc < S_; sc += 32) {
        {
            const int wb = pr * STW + pc * 2;
            uint32_t h, l;
            split_pack(pp.x, pp.y, h, l); sPh[wb]     = h; sPl[wb]     = l;
            split_pack(pp.z, pp.w, h, l); sPh[wb + 1] = h; sPl[wb + 1] = l;

            const int vb0 = vd * STW + sg0 * 2;
            const int vb1 = vd * STW + (sg0 + 4) * 2;
            split_pack(vv0[0], vv0[1], h, l); sVh[vb0]     = h; sVl[vb0]     = l;
            split_pack(vv0[2], vv0[3], h, l); sVh[vb0 + 1] = h; sVl[vb0 + 1] = l;
            split_pack(vv1[0], vv1[1], h, l); sVh[vb1]     = h; sVl[vb1]     = l;
            split_pack(vv1[2], vv1[3], h, l); sVh[vb1 + 1] = h; sVl[vb1 + 1] = l;
        }
        __syncthreads();

        if (sc + 32 < S_) {
            pp = *(const float4*)(Pb + (size_t)pr * S_ + sc + 32 + pc * 4);
#pragma unroll
            for (int k = 0; k < 4; k++) {
                vv0[k] = Vb[(size_t)(sc + 32 + sg0 * 4 + k) * D_ + vd];
                vv1[k] = Vb[(size_t)(sc + 32 + (sg0 + 4) * 4 + k) * D_ + vd];
            }
        }

#pragma unroll
        for (int ks = 0; ks < 2; ks++) {
            uint32_t ah[4], al[4];
            {
                const int base = (mw * 16 + g) * STW + ks * 8 + tg;
                ah[0] = sPh[base];               al[0] = sPl[base];
                ah[1] = sPh[base + 8 * STW];     al[1] = sPl[base + 8 * STW];
                ah[2] = sPh[base + 4];           al[2] = sPl[base + 4];
                ah[3] = sPh[base + 8 * STW + 4]; al[3] = sPl[base + 8 * STW + 4];
            }
#pragma unroll
            for (int nj = 0; nj < 4; nj++) {
                const int base = (nw * 32 + nj * 8 + g) * STW + ks * 8 + tg;
                uint32_t bh[2] = { sVh[base], sVh[base + 4] };
                uint32_t bl[2] = { sVl[base], sVl[base + 4] };
                mma16816(acc[nj], ah, bh);
                mma16816(acc[nj], ah, bl);
                mma16816(acc[nj], al, bh);
            }
        }
        __syncthreads();
    }

#pragma unroll
    for (int hh = 0; hh < 2; hh++) {
        const int q = q0 + mw * 16 + hh * 8 + g;
        float* orow = O + ((size_t)b * Q_ + q) * D_;
#pragma unroll
        for (int nj = 0; nj < 4; nj++) {
            const int d = nw * 32 + nj * 8 + tg * 2;
            float2 o = { acc[nj][hh * 2], acc[nj][hh * 2 + 1] };
            *(float2*)(orow + d) = o;
        }
    }
}

// ---------------------------------------------------------------------------
extern "C" void kernel_launch(void* const* d_in, const int* in_sizes, int n_in,
                              void* d_out, int out_size)
{
    const size_t MASK_N = (size_t)B_ * Q_ * S_;
    const void* mask = nullptr;
    const float* vkq[3] = {nullptr, nullptr, nullptr};
    int nv = 0;
    for (int i = 0; i < n_in; i++) {
        if ((size_t)in_sizes[i] == MASK_N && mask == nullptr) {
            mask = d_in[i];
        } else if (nv < 3) {
            vkq[nv++] = (const float*)d_in[i];
        }
    }
    const float* value = vkq[0];
    const float* key   = vkq[1];
    const float* query = vkq[2];

    float* out  = (float*)d_out;
    float* attn = out + (size_t)B_ * Q_ * D_;

    k_probe_mask<<<1, 1>>>((const unsigned int*)mask);

    dim3 g1(S_ / 128, Q_ / 128, B_);
    k_scores<<<g1, 512>>>(query, key, mask, attn);

    k_softmax<<<B_ * Q_, 256>>>(attn);

    dim3 g3(Q_ / 64, B_);
    k_pv<<<g3, 512>>>(attn, value, out);
}

// round 4
// speedup vs baseline: 2.9086x; 1.6327x over previous
#include <cuda_runtime.h>
#include <cuda_bf16.h>
#include <cstdint>

#define B_ 16
#define Q_ 2048
#define S_ 2048
#define D_ 128
#define NEG_INF __int_as_float(0xff800000)

// byte-level 128B swizzle (Swizzle<3,4,3>)
#define SWZ(o) ((o) ^ (((o) >> 3) & 0x70))

__device__ int g_mask_mode;   // 0 = uint8, 1 = int32, 2 = float32

// ---------------------------------------------------------------------------
__global__ void k_probe_mask(const unsigned int* __restrict__ m)
{
    bool is_i32 = true, is_f32 = true;
    for (int i = 0; i < 1024; i++) {
        unsigned int w = m[i];
        if (w > 1u) is_i32 = false;
        if (w != 0u && w != 0x3F800000u) is_f32 = false;
    }
    g_mask_mode = is_i32 ? 1 : (is_f32 ? 2 : 0);
}

// ---------------------------------------------------------------------------
__device__ __forceinline__ void split_pack(float x, float y, uint32_t& hi, uint32_t& lo)
{
    __nv_bfloat16 hx = __float2bfloat16_rn(x);
    __nv_bfloat16 hy = __float2bfloat16_rn(y);
    __nv_bfloat16 lx = __float2bfloat16_rn(x - __bfloat162float(hx));
    __nv_bfloat16 ly = __float2bfloat16_rn(y - __bfloat162float(hy));
    hi = (uint32_t)__bfloat16_as_ushort(hx) | ((uint32_t)__bfloat16_as_ushort(hy) << 16);
    lo = (uint32_t)__bfloat16_as_ushort(lx) | ((uint32_t)__bfloat16_as_ushort(ly) << 16);
}

// 8 consecutive floats (two float4) -> 8 bf16 hi (uint4) + 8 bf16 lo (uint4)
__device__ __forceinline__ void split8(const float4& a, const float4& b, uint4& hi, uint4& lo)
{
    split_pack(a.x, a.y, hi.x, lo.x);
    split_pack(a.z, a.w, hi.y, lo.y);
    split_pack(b.x, b.y, hi.z, lo.z);
    split_pack(b.z, b.w, hi.w, lo.w);
}

__device__ __forceinline__ void mma16816(float (&c)[4], const uint32_t (&a)[4], const uint32_t* b)
{
    asm volatile(
        "mma.sync.aligned.m16n8k16.row.col.f32.bf16.bf16.f32 "
        "{%0,%1,%2,%3}, {%4,%5,%6,%7}, {%8,%9}, {%0,%1,%2,%3};\n"
        : "+f"(c[0]), "+f"(c[1]), "+f"(c[2]), "+f"(c[3])
        : "r"(a[0]), "r"(a[1]), "r"(a[2]), "r"(a[3]), "r"(b[0]), "r"(b[1]));
}

__device__ __forceinline__ void ldsm_x4(uint32_t (&r)[4], uint32_t addr)
{
    asm volatile("ldmatrix.sync.aligned.m8n8.x4.shared.b16 {%0,%1,%2,%3}, [%4];\n"
                 : "=r"(r[0]), "=r"(r[1]), "=r"(r[2]), "=r"(r[3]) : "r"(addr));
}

__device__ __forceinline__ uint32_t sptr(const void* p)
{
    return (uint32_t)__cvta_generic_to_shared(p);
}

// ---------------------------------------------------------------------------
// Kernel 1: scores = mask ? -inf : (Q K^T) * D^-0.5  (3xBF16, ldmatrix feed)
// CTA 128q x 128s, 512 thr (16 warps 4x4, warp tile 32x32), D chunks of 32.
// ---------------------------------------------------------------------------
__global__ __launch_bounds__(512, 1) void k_scores(
    const float* __restrict__ Qm, const float* __restrict__ Km,
    const void* __restrict__ mask, float* __restrict__ P)
{
    // 4 tiles of 128 rows x 32 bf16 (64B rows, SW128-swizzled) = 8KB each
    __shared__ __align__(128) uint8_t sm[32768];
    uint8_t* sQh = sm;
    uint8_t* sQl = sm + 8192;
    uint8_t* sKh = sm + 16384;
    uint8_t* sKl = sm + 24576;

    const int b  = blockIdx.z;
    const int q0 = blockIdx.y * 128;
    const int s0 = blockIdx.x * 128;
    const float* Qb = Qm + ((size_t)b * Q_ + q0) * D_;
    const float* Kb = Km + ((size_t)b * S_ + s0) * D_;

    const int tid  = threadIdx.x;
    const int lane = tid & 31;
    const int wid  = tid >> 5;
    const int g    = lane >> 2;
    const int tg   = lane & 3;
    const int mw   = wid >> 2;
    const int nw   = wid & 3;

    float acc[2][4][4];
#pragma unroll
    for (int i = 0; i < 2; i++)
#pragma unroll
        for (int j = 0; j < 4; j++)
#pragma unroll
            for (int k = 0; k < 4; k++) acc[i][j][k] = 0.f;

    // conversion mapping: thread -> row r (0..127), 8-float chunk c (0..3)
    const int r = tid >> 2;
    const int c = tid & 3;
    const uint32_t sts_off = SWZ((uint32_t)(r * 64 + c * 16));

    float4 q0v, q1v, k0v, k1v;
    q0v = *(const float4*)(Qb + (size_t)r * D_ + c * 8);
    q1v = *(const float4*)(Qb + (size_t)r * D_ + c * 8 + 4);
    k0v = *(const float4*)(Kb + (size_t)r * D_ + c * 8);
    k1v = *(const float4*)(Kb + (size_t)r * D_ + c * 8 + 4);

    // precomputed ldmatrix lane offsets
    const uint32_t a_row[2] = { (uint32_t)(mw * 32 + 0  + (lane & 15)),
                                (uint32_t)(mw * 32 + 16 + (lane & 15)) };
    const uint32_t a_chq    = (uint32_t)(lane >> 4);           // + 2*ks
    const uint32_t b_row[2] = { (uint32_t)(nw * 32 + 0  + (lane & 7) + ((lane & 16) >> 1)),
                                (uint32_t)(nw * 32 + 16 + (lane & 7) + ((lane & 16) >> 1)) };
    const uint32_t b_chq    = (uint32_t)((lane >> 3) & 1);     // + 2*ks

    for (int dc = 0; dc < D_; dc += 32) {
        {
            uint4 h, l;
            split8(q0v, q1v, h, l);
            *(uint4*)(sQh + sts_off) = h;
            *(uint4*)(sQl + sts_off) = l;
            split8(k0v, k1v, h, l);
            *(uint4*)(sKh + sts_off) = h;
            *(uint4*)(sKl + sts_off) = l;
        }
        __syncthreads();

        if (dc + 32 < D_) {
            q0v = *(const float4*)(Qb + (size_t)r * D_ + dc + 32 + c * 8);
            q1v = *(const float4*)(Qb + (size_t)r * D_ + dc + 32 + c * 8 + 4);
            k0v = *(const float4*)(Kb + (size_t)r * D_ + dc + 32 + c * 8);
            k1v = *(const float4*)(Kb + (size_t)r * D_ + dc + 32 + c * 8 + 4);
        }

#pragma unroll
        for (int ks = 0; ks < 2; ks++) {
            uint32_t ah[2][4], al[2][4];
#pragma unroll
            for (int mi = 0; mi < 2; mi++) {
                uint32_t off = SWZ(a_row[mi] * 64 + (2 * ks + a_chq) * 16);
                ldsm_x4(ah[mi], sptr(sQh) + off);
                ldsm_x4(al[mi], sptr(sQl) + off);
            }
            uint32_t bh[2][4], bl[2][4];
#pragma unroll
            for (int njp = 0; njp < 2; njp++) {
                uint32_t off = SWZ(b_row[njp] * 64 + (2 * ks + b_chq) * 16);
                ldsm_x4(bh[njp], sptr(sKh) + off);
                ldsm_x4(bl[njp], sptr(sKl) + off);
            }
#pragma unroll
            for (int mi = 0; mi < 2; mi++)
#pragma unroll
                for (int njp = 0; njp < 2; njp++)
#pragma unroll
                    for (int j = 0; j < 2; j++) {
                        float (&cacc)[4] = acc[mi][njp * 2 + j];
                        mma16816(cacc, ah[mi], &bh[njp][2 * j]);
                        mma16816(cacc, ah[mi], &bl[njp][2 * j]);
                        mma16816(cacc, al[mi], &bh[njp][2 * j]);
                    }
        }
        __syncthreads();
    }

    const float scale = 0.08838834764831845f;  // 128^-0.5
    const int mm = g_mask_mode;
#pragma unroll
    for (int mi = 0; mi < 2; mi++) {
#pragma unroll
        for (int hh = 0; hh < 2; hh++) {
            const int q = q0 + mw * 32 + mi * 16 + hh * 8 + g;
            const size_t rowoff = ((size_t)b * Q_ + q) * (size_t)S_;
#pragma unroll
            for (int nj = 0; nj < 4; nj++) {
                const int s = s0 + nw * 32 + nj * 8 + tg * 2;
                const size_t off = rowoff + s;
                const float v0 = acc[mi][nj][hh * 2 + 0] * scale;
                const float v1 = acc[mi][nj][hh * 2 + 1] * scale;
                bool m0, m1;
                if (mm == 1) {
                    int2 w = *(const int2*)((const int*)mask + off);
                    m0 = w.x != 0; m1 = w.y != 0;
                } else if (mm == 2) {
                    float2 w = *(const float2*)((const float*)mask + off);
                    m0 = w.x != 0.f; m1 = w.y != 0.f;
                } else {
                    const unsigned char* mu = (const unsigned char*)mask + off;
                    m0 = mu[0] != 0; m1 = mu[1] != 0;
                }
                float2 o;
                o.x = m0 ? NEG_INF : v0;
                o.y = m1 ? NEG_INF : v1;
                *(float2*)(P + off) = o;
            }
        }
    }
}

// ---------------------------------------------------------------------------
// Kernel 2: in-place row softmax over S=2048. One block (256 thr) per row.
// ---------------------------------------------------------------------------
__global__ __launch_bounds__(256) void k_softmax(float* __restrict__ P)
{
    __shared__ float red[8];
    const size_t row = blockIdx.x;
    float* p = P + row * (size_t)S_;
    const int tid  = threadIdx.x;
    const int lane = tid & 31;
    const int wid  = tid >> 5;

    float4 v0 = ((const float4*)p)[tid];
    float4 v1 = ((const float4*)p)[tid + 256];

    float m = fmaxf(fmaxf(fmaxf(v0.x, v0.y), fmaxf(v0.z, v0.w)),
                    fmaxf(fmaxf(v1.x, v1.y), fmaxf(v1.z, v1.w)));
#pragma unroll
    for (int o = 16; o; o >>= 1) m = fmaxf(m, __shfl_xor_sync(0xffffffffu, m, o));
    if (lane == 0) red[wid] = m;
    __syncthreads();
    m = red[0];
#pragma unroll
    for (int w = 1; w < 8; w++) m = fmaxf(m, red[w]);
    __syncthreads();

    float e[8];
    e[0] = __expf(v0.x - m); e[1] = __expf(v0.y - m);
    e[2] = __expf(v0.z - m); e[3] = __expf(v0.w - m);
    e[4] = __expf(v1.x - m); e[5] = __expf(v1.y - m);
    e[6] = __expf(v1.z - m); e[7] = __expf(v1.w - m);
    float s = ((e[0] + e[1]) + (e[2] + e[3])) + ((e[4] + e[5]) + (e[6] + e[7]));
#pragma unroll
    for (int o = 16; o; o >>= 1) s += __shfl_xor_sync(0xffffffffu, s, o);
    if (lane == 0) red[wid] = s;
    __syncthreads();
    s = red[0];
#pragma unroll
    for (int w = 1; w < 8; w++) s += red[w];

    const float inv = 1.0f / s;
    v0.x = e[0] * inv; v0.y = e[1] * inv; v0.z = e[2] * inv; v0.w = e[3] * inv;
    v1.x = e[4] * inv; v1.y = e[5] * inv; v1.z = e[6] * inv; v1.w = e[7] * inv;
    ((float4*)p)[tid]       = v0;
    ((float4*)p)[tid + 256] = v1;
}

// ---------------------------------------------------------------------------
// Kernel 3: out = P @ V (3xBF16, ldmatrix feed).
// CTA 128q x 128d, 512 thr (16 warps 4x4, warp tile 32x32), S chunks of 32.
// V stored transposed [d][k] in smem (n-major rows, ldmatrix-compatible).
// ---------------------------------------------------------------------------
__global__ __launch_bounds__(512, 1) void k_pv(
    const float* __restrict__ P, const float* __restrict__ V,
    float* __restrict__ O)
{
    __shared__ __align__(128) uint8_t sm[32768];
    uint8_t* sPh = sm;
    uint8_t* sPl = sm + 8192;
    uint8_t* sVh = sm + 16384;
    uint8_t* sVl = sm + 24576;

    const int b  = blockIdx.y;
    const int q0 = blockIdx.x * 128;
    const float* Pb = P + ((size_t)b * Q_ + q0) * (size_t)S_;
    const float* Vb = V + (size_t)b * S_ * D_;

    const int tid  = threadIdx.x;
    const int lane = tid & 31;
    const int wid  = tid >> 5;
    const int g    = lane >> 2;
    const int tg   = lane & 3;
    const int mw   = wid >> 2;
    const int nw   = wid & 3;

    float acc[2][4][4];
#pragma unroll
    for (int i = 0; i < 2; i++)
#pragma unroll
        for (int j = 0; j < 4; j++)
#pragma unroll
            for (int k = 0; k < 4; k++) acc[i][j][k] = 0.f;

    // P conversion: thread -> q-row pr (0..127), 8-float k-chunk pc (0..3)
    const int pr = tid >> 2;
    const int pc = tid & 3;
    const uint32_t p_sts = SWZ((uint32_t)(pr * 64 + pc * 16));
    // V conversion: thread -> d-row vd (0..127), k-group sg (0..3), 8 scalars
    const int vd = tid & 127;
    const int sg = tid >> 7;
    const uint32_t v_sts = SWZ((uint32_t)(vd * 64 + sg * 16));

    const uint32_t a_row[2] = { (uint32_t)(mw * 32 + 0  + (lane & 15)),
                                (uint32_t)(mw * 32 + 16 + (lane & 15)) };
    const uint32_t a_chq    = (uint32_t)(lane >> 4);
    const uint32_t b_row[2] = { (uint32_t)(nw * 32 + 0  + (lane & 7) + ((lane & 16) >> 1)),
                                (uint32_t)(nw * 32 + 16 + (lane & 7) + ((lane & 16) >> 1)) };
    const uint32_t b_chq    = (uint32_t)((lane >> 3) & 1);

    float4 pp0, pp1;
    float vv[8];
    pp0 = *(const float4*)(Pb + (size_t)pr * S_ + pc * 8);
    pp1 = *(const float4*)(Pb + (size_t)pr * S_ + pc * 8 + 4);
#pragma unroll
    for (int k = 0; k < 8; k++)
        vv[k] = Vb[(size_t)(sg * 8 + k) * D_ + vd];

    for (int sc = 0; sc < S_; sc += 32) {
        {
            uint4 h, l;
            split8(pp0, pp1, h, l);
            *(uint4*)(sPh + p_sts) = h;
            *(uint4*)(sPl + p_sts) = l;
            float4 a = { vv[0], vv[1], vv[2], vv[3] };
            float4 bq = { vv[4], vv[5], vv[6], vv[7] };
            split8(a, bq, h, l);
            *(uint4*)(sVh + v_sts) = h;
            *(uint4*)(sVl + v_sts) = l;
        }
        __syncthreads();

        if (sc + 32 < S_) {
            pp0 = *(const float4*)(Pb + (size_t)pr * S_ + sc + 32 + pc * 8);
            pp1 = *(const float4*)(Pb + (size_t)pr * S_ + sc + 32 + pc * 8 + 4);
#pragma unroll
            for (int k = 0; k < 8; k++)
                vv[k] = Vb[(size_t)(sc + 32 + sg * 8 + k) * D_ + vd];
        }

#pragma unroll
        for (int ks = 0; ks < 2; ks++) {
            uint32_t ah[2][4], al[2][4];
#pragma unroll
            for (int mi = 0; mi < 2; mi++) {
                uint32_t off = SWZ(a_row[mi] * 64 + (2 * ks + a_chq) * 16);
                ldsm_x4(ah[mi], sptr(sPh) + off);
                ldsm_x4(al[mi], sptr(sPl) + off);
            }
            uint32_t bh[2][4], bl[2][4];
#pragma unroll
            for (int njp = 0; njp < 2; njp++) {
                uint32_t off = SWZ(b_row[njp] * 64 + (2 * ks + b_chq) * 16);
                ldsm_x4(bh[njp], sptr(sVh) + off);
                ldsm_x4(bl[njp], sptr(sVl) + off);
            }
#pragma unroll
            for (int mi = 0; mi < 2; mi++)
#pragma unroll
                for (int njp = 0; njp < 2; njp++)
#pragma unroll
                    for (int j = 0; j < 2; j++) {
                        float (&cacc)[4] = acc[mi][njp * 2 + j];
                        mma16816(cacc, ah[mi], &bh[njp][2 * j]);
                        mma16816(cacc, ah[mi], &bl[njp][2 * j]);
                        mma16816(cacc, al[mi], &bh[njp][2 * j]);
                    }
        }
        __syncthreads();
    }

#pragma unroll
    for (int mi = 0; mi < 2; mi++) {
#pragma unroll
        for (int hh = 0; hh < 2; hh++) {
            const int q = q0 + mw * 32 + mi * 16 + hh * 8 + g;
            float* orow = O + ((size_t)b * Q_ + q) * D_;
#pragma unroll
            for (int nj = 0; nj < 4; nj++) {
                const int d = nw * 32 + nj * 8 + tg * 2;
                float2 o = { acc[mi][nj][hh * 2], acc[mi][nj][hh * 2 + 1] };
                *(float2*)(orow + d) = o;
            }
        }
    }
}

// ---------------------------------------------------------------------------
extern "C" void kernel_launch(void* const* d_in, const int* in_sizes, int n_in,
                              void* d_out, int out_size)
{
    const size_t MASK_N = (size_t)B_ * Q_ * S_;
    const void* mask = nullptr;
    const float* vkq[3] = {nullptr, nullptr, nullptr};
    int nv = 0;
    for (int i = 0; i < n_in; i++) {
        if ((size_t)in_sizes[i] == MASK_N && mask == nullptr) {
            mask = d_in[i];
        } else if (nv < 3) {
            vkq[nv++] = (const float*)d_in[i];
        }
    }
    const float* value = vkq[0];
    const float* key   = vkq[1];
    const float* query = vkq[2];

    float* out  = (float*)d_out;
    float* attn = out + (size_t)B_ * Q_ * D_;

    k_probe_mask<<<1, 1>>>((const unsigned int*)mask);

    dim3 g1(S_ / 128, Q_ / 128, B_);
    k_scores<<<g1, 512>>>(query, key, mask, attn);

    k_softmax<<<B_ * Q_, 256>>>(attn);

    dim3 g3(Q_ / 128, B_);
    k_pv<<<g3, 512>>>(attn, value, out);
}